// round 6
// baseline (speedup 1.0000x reference)
#include <cuda_runtime.h>
#include <math.h>
#include <stdint.h>

#define N_ 512
#define L_ 65536
#define M_ 32768
#define TWO_PI 6.283185307179586f
#define PI_F   3.14159265358979f

// Scratch (allocation-free: __device__ globals)
__device__ ulonglong2 d_P0[N_];  // (-lam_im dup, -lam_re dup)
__device__ ulonglong2 d_P1[N_];  // (t0r dup, t0i dup)
__device__ ulonglong2 d_P2[N_];  // (t1r dup, t1i dup)
__device__ ulonglong2 d_P3[N_];  // (t2r dup, t2i dup)
__device__ ulonglong2 d_P4[N_];  // (t3r dup, t3i dup)
__device__ uint64_t   d_Lr2[N_]; // (lam_re^2 dup)
__device__ float  d_gscale;      // 2/step
__device__ float2 d_at[L_];      // atRoots (natural order)
__device__ float2 d_stage[L_];   // FFT intermediate (only M_ used)

__device__ __forceinline__ uint64_t pack2(float lo, float hi) {
    uint64_t r;
    asm("mov.b64 %0, {%1, %2};" : "=l"(r) : "r"(__float_as_uint(lo)), "r"(__float_as_uint(hi)));
    return r;
}
__device__ __forceinline__ void unpack2(uint64_t p, float& lo, float& hi) {
    uint32_t a, b;
    asm("mov.b64 {%0, %1}, %2;" : "=r"(a), "=r"(b) : "l"(p));
    lo = __uint_as_float(a); hi = __uint_as_float(b);
}
__device__ __forceinline__ uint64_t fma2(uint64_t a, uint64_t b, uint64_t c) {
    uint64_t d;
    asm("fma.rn.f32x2 %0, %1, %2, %3;" : "=l"(d) : "l"(a), "l"(b), "l"(c));
    return d;
}
__device__ __forceinline__ uint64_t add2(uint64_t a, uint64_t b) {
    uint64_t d;
    asm("add.rn.f32x2 %0, %1, %2;" : "=l"(d) : "l"(a), "l"(b));
    return d;
}
__device__ __forceinline__ uint64_t mul2(uint64_t a, uint64_t b) {
    uint64_t d;
    asm("mul.rn.f32x2 %0, %1, %2;" : "=l"(d) : "l"(a), "l"(b));
    return d;
}
__device__ __forceinline__ float frcp(float x) {
    float r; asm("rcp.approx.f32 %0, %1;" : "=f"(r) : "f"(x)); return r;
}

// ---------------------------------------------------------------------------
// Kernel 1: Bc = Vc @ B (one block per row, coalesced), duplicated tables.
// ---------------------------------------------------------------------------
__global__ void prep_kernel(const float* __restrict__ Lre, const float* __restrict__ Lim,
                            const float* __restrict__ pre, const float* __restrict__ pim,
                            const float* __restrict__ qre, const float* __restrict__ qim,
                            const float* __restrict__ Vre, const float* __restrict__ Vim,
                            const float* __restrict__ Ct,  const float* __restrict__ B,
                            const float* __restrict__ log_step) {
    int j = blockIdx.x;
    int t = threadIdx.x;

    const float* vr = Vre + j * N_;
    const float* vi = Vim + j * N_;
    float br = 0.f, bi = 0.f;
    #pragma unroll
    for (int i = t; i < N_; i += 128) {
        float b = __ldg(B + i);
        br += vr[i] * b;
        bi += vi[i] * b;
    }
    #pragma unroll
    for (int o = 16; o > 0; o >>= 1) {
        br += __shfl_down_sync(0xffffffffu, br, o);
        bi += __shfl_down_sync(0xffffffffu, bi, o);
    }
    __shared__ float sr[4], si[4];
    int w = t >> 5;
    if ((t & 31) == 0) { sr[w] = br; si[w] = bi; }
    __syncthreads();
    if (t == 0) {
        br = sr[0] + sr[1] + sr[2] + sr[3];
        bi = si[0] + si[1] + si[2] + si[3];

        // a0 = conj(Ct_c), a1 = conj(q), b0 = Bc, b1 = p
        float a0r = Ct[2 * j],  a0i = -Ct[2 * j + 1];
        float a1r = qre[j],     a1i = -qim[j];
        float b1r = pre[j],     b1i = pim[j];

        float t0r = a0r * br  - a0i * bi,  t0i = a0r * bi  + a0i * br;
        float t1r = a0r * b1r - a0i * b1i, t1i = a0r * b1i + a0i * b1r;
        float t2r = a1r * br  - a1i * bi,  t2i = a1r * bi  + a1i * br;
        float t3r = a1r * b1r - a1i * b1i, t3i = a1r * b1i + a1i * b1r;

        float lr = Lre[j], li = Lim[j];
        ulonglong2 v;
        v.x = pack2(-li, -li); v.y = pack2(-lr, -lr); d_P0[j] = v;
        v.x = pack2(t0r, t0r); v.y = pack2(t0i, t0i); d_P1[j] = v;
        v.x = pack2(t1r, t1r); v.y = pack2(t1i, t1i); d_P2[j] = v;
        v.x = pack2(t2r, t2r); v.y = pack2(t2i, t2i); d_P3[j] = v;
        v.x = pack2(t3r, t3r); v.y = pack2(t3i, t3i); d_P4[j] = v;
        d_Lr2[j] = pack2(lr * lr, lr * lr);
        if (j == 0) d_gscale = 2.0f / expf(log_step[0]);
    }
}

// ---------------------------------------------------------------------------
// Kernel 2: Cauchy reductions + low-rank correction -> atRoots.
// g = i*gs*tan(pi*l/L); c = 1 + i*tan(pi*l/L).
// 4 l-values per thread as two f32x2 packs (A: l, l+128; B: l+256, l+384).
// j split across block halves (h); partials combined through smem.
// Block 256 threads, grid 128. Tables amortized over 4 l's.
// ---------------------------------------------------------------------------
__global__ void __launch_bounds__(256) cauchy_kernel() {
    __shared__ ulonglong2 sP0[N_];
    __shared__ ulonglong2 sP1[N_];
    __shared__ ulonglong2 sP2[N_];
    __shared__ ulonglong2 sP3[N_];
    __shared__ ulonglong2 sP4[N_];
    __shared__ uint64_t   sLr2[N_];
    int t = threadIdx.x;
    #pragma unroll
    for (int i = t; i < N_; i += 256) {
        sP0[i] = d_P0[i];
        sP1[i] = d_P1[i];
        sP2[i] = d_P2[i];
        sP3[i] = d_P3[i];
        sP4[i] = d_P4[i];
        sLr2[i] = d_Lr2[i];
    }
    __syncthreads();

    int h = t >> 7;          // j-half
    int r = t & 127;
    float gs = d_gscale;
    int lb = blockIdx.x * 512 + r;   // l's: lb, lb+128, lb+256, lb+384

    float tn[4];
    #pragma unroll
    for (int u = 0; u < 4; u++) {
        float s, c;
        sincosf(PI_F * ((float)(lb + 128 * u) * (1.0f / (float)L_)), &s, &c);
        tn[u] = __fdividef(s, c);
    }
    uint64_t giA = pack2(gs * tn[0], gs * tn[1]);
    uint64_t giB = pack2(gs * tn[2], gs * tn[3]);

    uint64_t a00r = 0, a00i = 0, a01r = 0, a01i = 0;
    uint64_t a10r = 0, a10i = 0, a11r = 0, a11i = 0;
    uint64_t b00r = 0, b00i = 0, b01r = 0, b01i = 0;
    uint64_t b10r = 0, b10i = 0, b11r = 0, b11i = 0;
    const uint64_t SGN2 = 0x8000000080000000ull;

    int jbeg = h * 256, jend = jbeg + 256;
    #pragma unroll 2
    for (int j = jbeg; j < jend; j++) {
        ulonglong2 P0 = sP0[j];
        ulonglong2 P1 = sP1[j];
        ulonglong2 P2 = sP2[j];
        ulonglong2 P3 = sP3[j];
        ulonglong2 P4 = sP4[j];
        uint64_t lr2 = sLr2[j];

        uint64_t diA = add2(giA, P0.x);
        uint64_t diB = add2(giB, P0.x);
        uint64_t nA  = fma2(diA, diA, lr2);
        uint64_t nB  = fma2(diB, diB, lr2);
        float n0, n1, n2, n3;
        unpack2(nA, n0, n1);
        unpack2(nB, n2, n3);
        uint64_t rinvA = pack2(frcp(n0), frcp(n1));
        uint64_t rinvB = pack2(frcp(n2), frcp(n3));
        uint64_t rrA = mul2(P0.y, rinvA);
        uint64_t rrB = mul2(P0.y, rinvB);
        uint64_t mA  = mul2(diA, rinvA);
        uint64_t mB  = mul2(diB, rinvB);
        uint64_t nmA = mA ^ SGN2;
        uint64_t nmB = mB ^ SGN2;

        a00r = fma2(rrA, P1.x, a00r);  a00r = fma2(mA,  P1.y, a00r);
        a00i = fma2(rrA, P1.y, a00i);  a00i = fma2(nmA, P1.x, a00i);
        a01r = fma2(rrA, P2.x, a01r);  a01r = fma2(mA,  P2.y, a01r);
        a01i = fma2(rrA, P2.y, a01i);  a01i = fma2(nmA, P2.x, a01i);
        a10r = fma2(rrA, P3.x, a10r);  a10r = fma2(mA,  P3.y, a10r);
        a10i = fma2(rrA, P3.y, a10i);  a10i = fma2(nmA, P3.x, a10i);
        a11r = fma2(rrA, P4.x, a11r);  a11r = fma2(mA,  P4.y, a11r);
        a11i = fma2(rrA, P4.y, a11i);  a11i = fma2(nmA, P4.x, a11i);

        b00r = fma2(rrB, P1.x, b00r);  b00r = fma2(mB,  P1.y, b00r);
        b00i = fma2(rrB, P1.y, b00i);  b00i = fma2(nmB, P1.x, b00i);
        b01r = fma2(rrB, P2.x, b01r);  b01r = fma2(mB,  P2.y, b01r);
        b01i = fma2(rrB, P2.y, b01i);  b01i = fma2(nmB, P2.x, b01i);
        b10r = fma2(rrB, P3.x, b10r);  b10r = fma2(mB,  P3.y, b10r);
        b10i = fma2(rrB, P3.y, b10i);  b10i = fma2(nmB, P3.x, b10i);
        b11r = fma2(rrB, P4.x, b11r);  b11r = fma2(mB,  P4.y, b11r);
        b11i = fma2(rrB, P4.y, b11i);  b11i = fma2(nmB, P4.x, b11i);
    }

    // Combine j-halves: half 1 parks 16 partials in reused table smem.
    __syncthreads();
    if (h == 1) {
        sP0[4 * r]     = make_ulonglong2(a00r, a00i);
        sP0[4 * r + 1] = make_ulonglong2(a01r, a01i);
        sP0[4 * r + 2] = make_ulonglong2(a10r, a10i);
        sP0[4 * r + 3] = make_ulonglong2(a11r, a11i);
        sP1[4 * r]     = make_ulonglong2(b00r, b00i);
        sP1[4 * r + 1] = make_ulonglong2(b01r, b01i);
        sP1[4 * r + 2] = make_ulonglong2(b10r, b10i);
        sP1[4 * r + 3] = make_ulonglong2(b11r, b11i);
    }
    __syncthreads();
    if (h == 0) {
        ulonglong2 v;
        v = sP0[4 * r];     a00r = add2(a00r, v.x); a00i = add2(a00i, v.y);
        v = sP0[4 * r + 1]; a01r = add2(a01r, v.x); a01i = add2(a01i, v.y);
        v = sP0[4 * r + 2]; a10r = add2(a10r, v.x); a10i = add2(a10i, v.y);
        v = sP0[4 * r + 3]; a11r = add2(a11r, v.x); a11i = add2(a11i, v.y);
        v = sP1[4 * r];     b00r = add2(b00r, v.x); b00i = add2(b00i, v.y);
        v = sP1[4 * r + 1]; b01r = add2(b01r, v.x); b01i = add2(b01i, v.y);
        v = sP1[4 * r + 2]; b10r = add2(b10r, v.x); b10i = add2(b10i, v.y);
        v = sP1[4 * r + 3]; b11r = add2(b11r, v.x); b11i = add2(b11i, v.y);

        float k00r[4], k00i[4], k01r[4], k01i[4], k10r[4], k10i[4], k11r[4], k11i[4];
        unpack2(a00r, k00r[0], k00r[1]); unpack2(a00i, k00i[0], k00i[1]);
        unpack2(a01r, k01r[0], k01r[1]); unpack2(a01i, k01i[0], k01i[1]);
        unpack2(a10r, k10r[0], k10r[1]); unpack2(a10i, k10i[0], k10i[1]);
        unpack2(a11r, k11r[0], k11r[1]); unpack2(a11i, k11i[0], k11i[1]);
        unpack2(b00r, k00r[2], k00r[3]); unpack2(b00i, k00i[2], k00i[3]);
        unpack2(b01r, k01r[2], k01r[3]); unpack2(b01i, k01i[2], k01i[3]);
        unpack2(b10r, k10r[2], k10r[3]); unpack2(b10i, k10i[2], k10i[3]);
        unpack2(b11r, k11r[2], k11r[3]); unpack2(b11i, k11i[2], k11i[3]);

        #pragma unroll
        for (int u = 0; u < 4; u++) {
            int l = lb + 128 * u;
            // atRoots = (1 + i*tan) * (k00 - k01*k10/(1+k11))
            float ddr = 1.f + k11r[u], ddi = k11i[u];
            float dinv = __fdividef(1.f, ddr * ddr + ddi * ddi);
            float qr = k01r[u] * k10r[u] - k01i[u] * k10i[u];
            float qi = k01r[u] * k10i[u] + k01i[u] * k10r[u];
            float qdr = (qr * ddr + qi * ddi) * dinv;
            float qdi = (qi * ddr - qr * ddi) * dinv;
            float ar = k00r[u] - qdr;
            float ai = k00i[u] - qdi;
            float tv = tn[u];
            d_at[l] = make_float2(ar - tv * ai, ai + tv * ar);
        }
    }
}

// ---------------------------------------------------------------------------
// Real-output IFFT of length L via complex IFFT of length M = L/2 = 256x128.
//   G[k] = (X[k]+conj(X[L-k]))(1+i w_k) + (X[k+M]+conj(X[M-k]))(1-i w_k)
//   z = (1/(2L)) * sum_k G[k] e^{+2pi i k m / M};  out[2m]=Re z, out[2m+1]=Im z
// Four-step: k = a + 256 b (a in 256, b in 128); m = c + 128 d.
// ---------------------------------------------------------------------------
__global__ void __launch_bounds__(128) fft_step1() {
    __shared__ float2 sx[128];
    __shared__ float2 sw[128];       // e^{+2pi i k/128}
    __shared__ float2 sz[16 * 9];    // padded
    int a = blockIdx.x, t = threadIdx.x;   // t = b index

    // Build G[a + 256 t]
    {
        int k1 = a + 256 * t;
        float2 X1 = d_at[k1];
        float2 X2 = d_at[(L_ - k1) & (L_ - 1)];
        float2 X3 = d_at[k1 + M_];
        float2 X4 = d_at[M_ - k1];
        float Ar = X1.x + X2.x, Ai = X1.y - X2.y;
        float Br = X3.x + X4.x, Bi = X3.y - X4.y;
        float ws, wc;
        __sincosf(TWO_PI * ((float)k1 * (1.0f / (float)L_)), &ws, &wc);
        float Qr = Ar - Br, Qi = Ai - Bi;
        float wqr = wc * Qr - ws * Qi;
        float wqi = wc * Qi + ws * Qr;
        sx[t] = make_float2(Ar + Br - wqi, Ai + Bi + wqr);
        float s, c;
        __sincosf(TWO_PI * ((float)t * (1.0f / 128.0f)), &s, &c);
        sw[t] = make_float2(c, s);
    }
    __syncthreads();

    // Stage A: z[b1][c1] over b2 in [0,8): b1 in 16, c1 in 8
    {
        int b1 = t & 15, c1 = t >> 4;
        float xr = 0.f, xi = 0.f;
        #pragma unroll
        for (int b2 = 0; b2 < 8; b2++) {
            float2 x = sx[b1 + 16 * b2];
            float2 w = sw[(16 * b2 * c1) & 127];
            xr += x.x * w.x - x.y * w.y;
            xi += x.x * w.y + x.y * w.x;
        }
        float2 tw = sw[(b1 * c1) & 127];
        sz[b1 * 9 + c1] = make_float2(xr * tw.x - xi * tw.y,
                                      xr * tw.y + xi * tw.x);
    }
    __syncthreads();

    // Stage B: S[c1 + 8 c2] = sum_b1 z[b1][c1] W16^{b1 c2};  c = t
    {
        int c1 = t & 7, c2 = t >> 3;
        float yr = 0.f, yi = 0.f;
        #pragma unroll
        for (int b1 = 0; b1 < 16; b1++) {
            float2 z = sz[b1 * 9 + c1];
            float2 w = sw[(8 * b1 * c2) & 127];
            yr += z.x * w.x - z.y * w.y;
            yi += z.x * w.y + z.y * w.x;
        }
        int m = (a * t) & (M_ - 1);
        float ws, wc;
        __sincosf(TWO_PI * ((float)m * (1.0f / (float)M_)), &ws, &wc);
        d_stage[t * 256 + a] = make_float2(yr * wc - yi * ws,
                                           yr * ws + yi * wc);
    }
}

// Each column-DFT (256-pt) split across 2 blocks: block = (c, half).
// grid 256 blocks x 128 threads.
__global__ void __launch_bounds__(128) fft_step2(float2* __restrict__ out) {
    __shared__ float2 sx[256];
    __shared__ float2 sw[256];
    __shared__ float2 sz[16 * 17];
    int blk = blockIdx.x;
    int c = blk >> 1;
    int half = blk & 1;
    int t = threadIdx.x;   // 0..127

    sx[t]       = d_stage[c * 256 + t];
    sx[t + 128] = d_stage[c * 256 + t + 128];
    {
        float s, cc;
        __sincosf(TWO_PI * ((float)t * (1.0f / 256.0f)), &s, &cc);
        sw[t] = make_float2(cc, s);
        __sincosf(TWO_PI * ((float)(t + 128) * (1.0f / 256.0f)), &s, &cc);
        sw[t + 128] = make_float2(cc, s);
    }
    __syncthreads();

    // Stage A: all 256 z values; each thread does 2.
    #pragma unroll
    for (int e2 = 0; e2 < 2; e2++) {
        int e = t + 128 * e2;
        int a1 = e & 15, d1 = e >> 4;
        float xr = 0.f, xi = 0.f;
        #pragma unroll
        for (int a2 = 0; a2 < 16; a2++) {
            float2 x = sx[a1 + 16 * a2];
            float2 w = sw[(16 * a2 * d1) & 255];
            xr += x.x * w.x - x.y * w.y;
            xi += x.x * w.y + x.y * w.x;
        }
        float2 tw = sw[a1 * d1];
        sz[a1 * 17 + d1] = make_float2(xr * tw.x - xi * tw.y,
                                       xr * tw.y + xi * tw.x);
    }
    __syncthreads();

    // Stage B: this block's 128 outputs: d = half*128 + t
    {
        int d = half * 128 + t;
        int d1 = d & 15, d2 = d >> 4;
        float yr = 0.f, yi = 0.f;
        #pragma unroll
        for (int a1 = 0; a1 < 16; a1++) {
            float2 z = sz[a1 * 17 + d1];
            float2 w = sw[(16 * a1 * d2) & 255];
            yr += z.x * w.x - z.y * w.y;
            yi += z.x * w.y + z.y * w.x;
        }
        const float sc = 1.0f / (2.0f * (float)L_);
        out[c + 128 * d] = make_float2(yr * sc, yi * sc);
    }
}

// ---------------------------------------------------------------------------
extern "C" void kernel_launch(void* const* d_in, const int* in_sizes, int n_in,
                              void* d_out, int out_size) {
    const float* Lambda_re = (const float*)d_in[0];
    const float* Lambda_im = (const float*)d_in[1];
    const float* p_re      = (const float*)d_in[2];
    const float* p_im      = (const float*)d_in[3];
    const float* q_re      = (const float*)d_in[4];
    const float* q_im      = (const float*)d_in[5];
    const float* Vc_re     = (const float*)d_in[6];
    const float* Vc_im     = (const float*)d_in[7];
    const float* Ct        = (const float*)d_in[8];
    const float* B         = (const float*)d_in[9];
    const float* log_step  = (const float*)d_in[10];

    prep_kernel<<<N_, 128>>>(Lambda_re, Lambda_im, p_re, p_im, q_re, q_im,
                             Vc_re, Vc_im, Ct, B, log_step);
    cauchy_kernel<<<L_ / 512, 256>>>();
    fft_step1<<<256, 128>>>();
    fft_step2<<<256, 128>>>((float2*)d_out);
}

// round 7
// speedup vs baseline: 1.1713x; 1.1713x over previous
#include <cuda_runtime.h>
#include <math.h>
#include <stdint.h>

#define N_ 512
#define L_ 65536
#define M_ 32768
#define NMOM 24
#define TWO_PI 6.283185307179586f
#define PI_F   3.14159265358979f

// Scratch (allocation-free: __device__ globals)
__device__ ulonglong2 d_P0[N_];  // (-lam_im dup, -lam_re dup)
__device__ ulonglong2 d_P1[N_];  // (t0r dup, t0i dup)
__device__ ulonglong2 d_P2[N_];  // (t1r dup, t1i dup)
__device__ ulonglong2 d_P3[N_];  // (t2r dup, t2i dup)
__device__ ulonglong2 d_P4[N_];  // (t3r dup, t3i dup)
__device__ uint64_t   d_Lr2[N_]; // (lam_re^2 dup)
__device__ float2 d_lamc[N_];    // (lam_re, lam_im)
__device__ float4 d_tA[N_];      // (t0r,t0i,t1r,t1i)
__device__ float4 d_tB[N_];      // (t2r,t2i,t3r,t3i)
__device__ float4 d_mom[NMOM][2];// moments: [m][0]=(C00r,C00i,C01r,C01i) [m][1]=(C10..C11)
__device__ float  d_R2;          // (2*max|lam|)^2 near-threshold on y^2
__device__ float  d_gscale;      // 2/step
__device__ float2 d_at[L_];      // atRoots (natural order)
__device__ float2 d_stage[L_];   // FFT intermediate (only M_ used)

__device__ __forceinline__ uint64_t pack2(float lo, float hi) {
    uint64_t r;
    asm("mov.b64 %0, {%1, %2};" : "=l"(r) : "r"(__float_as_uint(lo)), "r"(__float_as_uint(hi)));
    return r;
}
__device__ __forceinline__ void unpack2(uint64_t p, float& lo, float& hi) {
    uint32_t a, b;
    asm("mov.b64 {%0, %1}, %2;" : "=r"(a), "=r"(b) : "l"(p));
    lo = __uint_as_float(a); hi = __uint_as_float(b);
}
__device__ __forceinline__ uint64_t fma2(uint64_t a, uint64_t b, uint64_t c) {
    uint64_t d;
    asm("fma.rn.f32x2 %0, %1, %2, %3;" : "=l"(d) : "l"(a), "l"(b), "l"(c));
    return d;
}
__device__ __forceinline__ uint64_t add2(uint64_t a, uint64_t b) {
    uint64_t d;
    asm("add.rn.f32x2 %0, %1, %2;" : "=l"(d) : "l"(a), "l"(b));
    return d;
}
__device__ __forceinline__ uint64_t mul2(uint64_t a, uint64_t b) {
    uint64_t d;
    asm("mul.rn.f32x2 %0, %1, %2;" : "=l"(d) : "l"(a), "l"(b));
    return d;
}
__device__ __forceinline__ float frcp(float x) {
    float r; asm("rcp.approx.f32 %0, %1;" : "=f"(r) : "f"(x)); return r;
}

// ---------------------------------------------------------------------------
// Kernel 1: Bc = Vc @ B (one block per row, coalesced), tables.
// ---------------------------------------------------------------------------
__global__ void prep_kernel(const float* __restrict__ Lre, const float* __restrict__ Lim,
                            const float* __restrict__ pre, const float* __restrict__ pim,
                            const float* __restrict__ qre, const float* __restrict__ qim,
                            const float* __restrict__ Vre, const float* __restrict__ Vim,
                            const float* __restrict__ Ct,  const float* __restrict__ B,
                            const float* __restrict__ log_step) {
    int j = blockIdx.x;
    int t = threadIdx.x;

    const float* vr = Vre + j * N_;
    const float* vi = Vim + j * N_;
    float br = 0.f, bi = 0.f;
    #pragma unroll
    for (int i = t; i < N_; i += 128) {
        float b = __ldg(B + i);
        br += vr[i] * b;
        bi += vi[i] * b;
    }
    #pragma unroll
    for (int o = 16; o > 0; o >>= 1) {
        br += __shfl_down_sync(0xffffffffu, br, o);
        bi += __shfl_down_sync(0xffffffffu, bi, o);
    }
    __shared__ float sr[4], si[4];
    int w = t >> 5;
    if ((t & 31) == 0) { sr[w] = br; si[w] = bi; }
    __syncthreads();
    if (t == 0) {
        br = sr[0] + sr[1] + sr[2] + sr[3];
        bi = si[0] + si[1] + si[2] + si[3];

        // a0 = conj(Ct_c), a1 = conj(q), b0 = Bc, b1 = p
        float a0r = Ct[2 * j],  a0i = -Ct[2 * j + 1];
        float a1r = qre[j],     a1i = -qim[j];
        float b1r = pre[j],     b1i = pim[j];

        float t0r = a0r * br  - a0i * bi,  t0i = a0r * bi  + a0i * br;
        float t1r = a0r * b1r - a0i * b1i, t1i = a0r * b1i + a0i * b1r;
        float t2r = a1r * br  - a1i * bi,  t2i = a1r * bi  + a1i * br;
        float t3r = a1r * b1r - a1i * b1i, t3i = a1r * b1i + a1i * b1r;

        float lr = Lre[j], li = Lim[j];
        ulonglong2 v;
        v.x = pack2(-li, -li); v.y = pack2(-lr, -lr); d_P0[j] = v;
        v.x = pack2(t0r, t0r); v.y = pack2(t0i, t0i); d_P1[j] = v;
        v.x = pack2(t1r, t1r); v.y = pack2(t1i, t1i); d_P2[j] = v;
        v.x = pack2(t2r, t2r); v.y = pack2(t2i, t2i); d_P3[j] = v;
        v.x = pack2(t3r, t3r); v.y = pack2(t3i, t3i); d_P4[j] = v;
        d_Lr2[j] = pack2(lr * lr, lr * lr);
        d_lamc[j] = make_float2(lr, li);
        d_tA[j] = make_float4(t0r, t0i, t1r, t1i);
        d_tB[j] = make_float4(t2r, t2i, t3r, t3i);
        if (j == 0) d_gscale = 2.0f / expf(log_step[0]);
    }
}

// ---------------------------------------------------------------------------
// Kernel 1b: moments C_m = sum_j t_j * lam_j^m, m in [0, NMOM); plus near
// threshold R2 = (2*max|lam|)^2. One warp-block per m.
// ---------------------------------------------------------------------------
__global__ void moments_kernel() {
    int m = blockIdx.x;
    int lane = threadIdx.x;

    float a00r = 0.f, a00i = 0.f, a01r = 0.f, a01i = 0.f;
    float a10r = 0.f, a10i = 0.f, a11r = 0.f, a11i = 0.f;
    float mx = 0.f;

    for (int i = 0; i < 16; i++) {
        int j = lane + 32 * i;
        float2 lam = d_lamc[j];
        float4 tA = d_tA[j];
        float4 tB = d_tB[j];
        // lam^m by binary power
        float pr = 1.f, pi = 0.f, br = lam.x, bi = lam.y;
        int e = m;
        while (e) {
            if (e & 1) { float nr = pr * br - pi * bi; pi = pr * bi + pi * br; pr = nr; }
            float b2 = br * br - bi * bi; bi = 2.f * br * bi; br = b2;
            e >>= 1;
        }
        a00r += tA.x * pr - tA.y * pi;  a00i += tA.x * pi + tA.y * pr;
        a01r += tA.z * pr - tA.w * pi;  a01i += tA.z * pi + tA.w * pr;
        a10r += tB.x * pr - tB.y * pi;  a10i += tB.x * pi + tB.y * pr;
        a11r += tB.z * pr - tB.w * pi;  a11i += tB.z * pi + tB.w * pr;
        mx = fmaxf(mx, lam.x * lam.x + lam.y * lam.y);
    }
    #pragma unroll
    for (int o = 16; o > 0; o >>= 1) {
        a00r += __shfl_down_sync(0xffffffffu, a00r, o);
        a00i += __shfl_down_sync(0xffffffffu, a00i, o);
        a01r += __shfl_down_sync(0xffffffffu, a01r, o);
        a01i += __shfl_down_sync(0xffffffffu, a01i, o);
        a10r += __shfl_down_sync(0xffffffffu, a10r, o);
        a10i += __shfl_down_sync(0xffffffffu, a10i, o);
        a11r += __shfl_down_sync(0xffffffffu, a11r, o);
        a11i += __shfl_down_sync(0xffffffffu, a11i, o);
        mx = fmaxf(mx, __shfl_down_sync(0xffffffffu, mx, o));
    }
    if (lane == 0) {
        d_mom[m][0] = make_float4(a00r, a00i, a01r, a01i);
        d_mom[m][1] = make_float4(a10r, a10i, a11r, a11i);
        if (m == 0) d_R2 = 4.0f * mx;
    }
}

// ---------------------------------------------------------------------------
// Kernel 2: Cauchy -> atRoots. g = i*y, y = gs*tan(pi*l/L).
// Warp window remap V = w*256 + B spreads near-l warps across all blocks.
// Near (|y| < 2 max|lam|): exact 512-j f32x2 loop. Far: 24-term Horner in
// 1/g using precomputed moments (error ~0.5^24).
// ---------------------------------------------------------------------------
__global__ void __launch_bounds__(128) cauchy_kernel() {
    __shared__ ulonglong2 sP0[N_];
    __shared__ ulonglong2 sP1[N_];
    __shared__ ulonglong2 sP2[N_];
    __shared__ ulonglong2 sP3[N_];
    __shared__ ulonglong2 sP4[N_];
    __shared__ uint64_t   sLr2[N_];
    __shared__ float4     smom[NMOM][2];

    int t = threadIdx.x, B = blockIdx.x;
    int w = t >> 5, lane = t & 31;
    int V = w * 256 + B;               // window id in [0,1024)
    int l0 = V * 64 + lane;
    int l1 = l0 + 32;

    float gs = d_gscale, R2 = d_R2;

    float tan0, tan1;
    {
        float s, c;
        sincosf(PI_F * ((float)l0 * (1.0f / (float)L_)), &s, &c);
        tan0 = __fdividef(s, c);
        sincosf(PI_F * ((float)l1 * (1.0f / (float)L_)), &s, &c);
        tan1 = __fdividef(s, c);
    }
    float y0 = gs * tan0, y1 = gs * tan1;
    int near = (y0 * y0 < R2) || (y1 * y1 < R2);
    int blockNear = __syncthreads_or(near);

    if (t < NMOM * 2) ((float4*)smom)[t] = ((const float4*)d_mom)[t];
    if (blockNear) {
        #pragma unroll
        for (int i = t; i < N_; i += 128) {
            sP0[i] = d_P0[i];
            sP1[i] = d_P1[i];
            sP2[i] = d_P2[i];
            sP3[i] = d_P3[i];
            sP4[i] = d_P4[i];
            sLr2[i] = d_Lr2[i];
        }
    }
    __syncthreads();

    float k00r[2], k00i[2], k01r[2], k01i[2], k10r[2], k10i[2], k11r[2], k11i[2];

    if (__any_sync(0xffffffffu, near)) {
        // ---- exact path: f32x2 over all 512 poles, lanes = (l0, l1) ----
        uint64_t gi2 = pack2(y0, y1);
        uint64_t c00r = 0, c00i = 0, c01r = 0, c01i = 0;
        uint64_t c10r = 0, c10i = 0, c11r = 0, c11i = 0;
        const uint64_t SGN2 = 0x8000000080000000ull;

        #pragma unroll 4
        for (int j = 0; j < N_; j++) {
            ulonglong2 P0 = sP0[j];
            ulonglong2 P1 = sP1[j];
            ulonglong2 P2 = sP2[j];
            ulonglong2 P3 = sP3[j];
            ulonglong2 P4 = sP4[j];
            uint64_t lr2 = sLr2[j];
            uint64_t di2   = add2(gi2, P0.x);
            uint64_t n2    = fma2(di2, di2, lr2);
            float nlo, nhi;
            unpack2(n2, nlo, nhi);
            uint64_t rinv2 = pack2(frcp(nlo), frcp(nhi));
            uint64_t rr2   = mul2(P0.y, rinv2);
            uint64_t m2    = mul2(di2, rinv2);
            uint64_t nm2   = m2 ^ SGN2;

            c00r = fma2(rr2, P1.x, c00r);  c00r = fma2(m2,  P1.y, c00r);
            c00i = fma2(rr2, P1.y, c00i);  c00i = fma2(nm2, P1.x, c00i);
            c01r = fma2(rr2, P2.x, c01r);  c01r = fma2(m2,  P2.y, c01r);
            c01i = fma2(rr2, P2.y, c01i);  c01i = fma2(nm2, P2.x, c01i);
            c10r = fma2(rr2, P3.x, c10r);  c10r = fma2(m2,  P3.y, c10r);
            c10i = fma2(rr2, P3.y, c10i);  c10i = fma2(nm2, P3.x, c10i);
            c11r = fma2(rr2, P4.x, c11r);  c11r = fma2(m2,  P4.y, c11r);
            c11i = fma2(rr2, P4.y, c11i);  c11i = fma2(nm2, P4.x, c11i);
        }
        unpack2(c00r, k00r[0], k00r[1]); unpack2(c00i, k00i[0], k00i[1]);
        unpack2(c01r, k01r[0], k01r[1]); unpack2(c01i, k01i[0], k01i[1]);
        unpack2(c10r, k10r[0], k10r[1]); unpack2(c10i, k10i[0], k10i[1]);
        unpack2(c11r, k11r[0], k11r[1]); unpack2(c11i, k11i[0], k11i[1]);
    } else {
        // ---- far path: Horner in w = 1/g = -i*u, u = 1/y ----
        #pragma unroll
        for (int u = 0; u < 2; u++) {
            float y = u ? y1 : y0;
            float uu = frcp(y);
            float4 A = smom[NMOM - 1][0], Bm = smom[NMOM - 1][1];
            float h0r = A.x,  h0i = A.y,  h1r = A.z,  h1i = A.w;
            float h2r = Bm.x, h2i = Bm.y, h3r = Bm.z, h3i = Bm.w;
            #pragma unroll
            for (int m = NMOM - 2; m >= 0; m--) {
                float4 A2 = smom[m][0], B2 = smom[m][1];
                float n0r = fmaf(h0i, uu, A2.x), n0i = fmaf(-h0r, uu, A2.y);
                float n1r = fmaf(h1i, uu, A2.z), n1i = fmaf(-h1r, uu, A2.w);
                float n2r = fmaf(h2i, uu, B2.x), n2i = fmaf(-h2r, uu, B2.y);
                float n3r = fmaf(h3i, uu, B2.z), n3i = fmaf(-h3r, uu, B2.w);
                h0r = n0r; h0i = n0i; h1r = n1r; h1i = n1i;
                h2r = n2r; h2i = n2i; h3r = n3r; h3i = n3i;
            }
            k00r[u] = h0i * uu;  k00i[u] = -h0r * uu;
            k01r[u] = h1i * uu;  k01i[u] = -h1r * uu;
            k10r[u] = h2i * uu;  k10i[u] = -h2r * uu;
            k11r[u] = h3i * uu;  k11i[u] = -h3r * uu;
        }
    }

    float tn[2] = {tan0, tan1};
    #pragma unroll
    for (int u = 0; u < 2; u++) {
        int l = u ? l1 : l0;
        // atRoots = (1 + i*tan) * (k00 - k01*k10/(1+k11))
        float ddr = 1.f + k11r[u], ddi = k11i[u];
        float dinv = __fdividef(1.f, ddr * ddr + ddi * ddi);
        float qr = k01r[u] * k10r[u] - k01i[u] * k10i[u];
        float qi = k01r[u] * k10i[u] + k01i[u] * k10r[u];
        float qdr = (qr * ddr + qi * ddi) * dinv;
        float qdi = (qi * ddr - qr * ddi) * dinv;
        float ar = k00r[u] - qdr;
        float ai = k00i[u] - qdi;
        float tv = tn[u];
        d_at[l] = make_float2(ar - tv * ai, ai + tv * ar);
    }
}

// ---------------------------------------------------------------------------
// Real-output IFFT of length L via complex IFFT of length M = L/2 = 256x128.
//   G[k] = (X[k]+conj(X[L-k]))(1+i w_k) + (X[k+M]+conj(X[M-k]))(1-i w_k)
//   z = (1/(2L)) * sum_k G[k] e^{+2pi i k m / M};  out[2m]=Re z, out[2m+1]=Im z
// Four-step: k = a + 256 b (a in 256, b in 128); m = c + 128 d.
// ---------------------------------------------------------------------------
__global__ void __launch_bounds__(128) fft_step1() {
    __shared__ float2 sx[128];
    __shared__ float2 sw[128];       // e^{+2pi i k/128}
    __shared__ float2 sz[16 * 9];    // padded
    int a = blockIdx.x, t = threadIdx.x;   // t = b index

    // Build G[a + 256 t]
    {
        int k1 = a + 256 * t;
        float2 X1 = d_at[k1];
        float2 X2 = d_at[(L_ - k1) & (L_ - 1)];
        float2 X3 = d_at[k1 + M_];
        float2 X4 = d_at[M_ - k1];
        float Ar = X1.x + X2.x, Ai = X1.y - X2.y;
        float Br = X3.x + X4.x, Bi = X3.y - X4.y;
        float ws, wc;
        __sincosf(TWO_PI * ((float)k1 * (1.0f / (float)L_)), &ws, &wc);
        float Qr = Ar - Br, Qi = Ai - Bi;
        float wqr = wc * Qr - ws * Qi;
        float wqi = wc * Qi + ws * Qr;
        sx[t] = make_float2(Ar + Br - wqi, Ai + Bi + wqr);
        float s, c;
        __sincosf(TWO_PI * ((float)t * (1.0f / 128.0f)), &s, &c);
        sw[t] = make_float2(c, s);
    }
    __syncthreads();

    // Stage A: z[b1][c1] over b2 in [0,8): b1 in 16, c1 in 8
    {
        int b1 = t & 15, c1 = t >> 4;
        float xr = 0.f, xi = 0.f;
        #pragma unroll
        for (int b2 = 0; b2 < 8; b2++) {
            float2 x = sx[b1 + 16 * b2];
            float2 w = sw[(16 * b2 * c1) & 127];
            xr += x.x * w.x - x.y * w.y;
            xi += x.x * w.y + x.y * w.x;
        }
        float2 tw = sw[(b1 * c1) & 127];
        sz[b1 * 9 + c1] = make_float2(xr * tw.x - xi * tw.y,
                                      xr * tw.y + xi * tw.x);
    }
    __syncthreads();

    // Stage B: S[c1 + 8 c2] = sum_b1 z[b1][c1] W16^{b1 c2};  c = t
    {
        int c1 = t & 7, c2 = t >> 3;
        float yr = 0.f, yi = 0.f;
        #pragma unroll
        for (int b1 = 0; b1 < 16; b1++) {
            float2 z = sz[b1 * 9 + c1];
            float2 w = sw[(8 * b1 * c2) & 127];
            yr += z.x * w.x - z.y * w.y;
            yi += z.x * w.y + z.y * w.x;
        }
        int m = (a * t) & (M_ - 1);
        float ws, wc;
        __sincosf(TWO_PI * ((float)m * (1.0f / (float)M_)), &ws, &wc);
        d_stage[t * 256 + a] = make_float2(yr * wc - yi * ws,
                                           yr * ws + yi * wc);
    }
}

__global__ void __launch_bounds__(256) fft_step2(float2* __restrict__ out) {
    __shared__ float2 sx[256];
    __shared__ float2 sw[256];
    __shared__ float2 sz[16 * 17];
    int c = blockIdx.x, t = threadIdx.x;   // t = d index

    sx[t] = d_stage[c * 256 + t];
    {
        float s, cc;
        __sincosf(TWO_PI * ((float)t * (1.0f / 256.0f)), &s, &cc);
        sw[t] = make_float2(cc, s);
    }
    __syncthreads();

    {
        int a1 = t & 15, d1 = t >> 4;
        float xr = 0.f, xi = 0.f;
        #pragma unroll
        for (int a2 = 0; a2 < 16; a2++) {
            float2 x = sx[a1 + 16 * a2];
            float2 w = sw[(16 * a2 * d1) & 255];
            xr += x.x * w.x - x.y * w.y;
            xi += x.x * w.y + x.y * w.x;
        }
        float2 tw = sw[a1 * d1];
        sz[a1 * 17 + d1] = make_float2(xr * tw.x - xi * tw.y,
                                       xr * tw.y + xi * tw.x);
    }
    __syncthreads();

    {
        int d1 = t & 15, d2 = t >> 4;
        float yr = 0.f, yi = 0.f;
        #pragma unroll
        for (int a1 = 0; a1 < 16; a1++) {
            float2 z = sz[a1 * 17 + d1];
            float2 w = sw[(16 * a1 * d2) & 255];
            yr += z.x * w.x - z.y * w.y;
            yi += z.x * w.y + z.y * w.x;
        }
        const float sc = 1.0f / (2.0f * (float)L_);
        out[c + 128 * t] = make_float2(yr * sc, yi * sc);
    }
}

// ---------------------------------------------------------------------------
extern "C" void kernel_launch(void* const* d_in, const int* in_sizes, int n_in,
                              void* d_out, int out_size) {
    const float* Lambda_re = (const float*)d_in[0];
    const float* Lambda_im = (const float*)d_in[1];
    const float* p_re      = (const float*)d_in[2];
    const float* p_im      = (const float*)d_in[3];
    const float* q_re      = (const float*)d_in[4];
    const float* q_im      = (const float*)d_in[5];
    const float* Vc_re     = (const float*)d_in[6];
    const float* Vc_im     = (const float*)d_in[7];
    const float* Ct        = (const float*)d_in[8];
    const float* B         = (const float*)d_in[9];
    const float* log_step  = (const float*)d_in[10];

    prep_kernel<<<N_, 128>>>(Lambda_re, Lambda_im, p_re, p_im, q_re, q_im,
                             Vc_re, Vc_im, Ct, B, log_step);
    moments_kernel<<<NMOM, 32>>>();
    cauchy_kernel<<<256, 128>>>();
    fft_step1<<<256, 128>>>();
    fft_step2<<<128, 256>>>((float2*)d_out);
}

// round 8
// speedup vs baseline: 1.5109x; 1.2899x over previous
#include <cuda_runtime.h>
#include <math.h>
#include <stdint.h>

#define N_ 512
#define L_ 65536
#define M_ 32768
#define NMOM 24
#define TWO_PI 6.283185307179586f
#define PI_F   3.14159265358979f

// Scratch (allocation-free: __device__ globals)
__device__ ulonglong2 d_P0[N_];  // (-lam_im dup, -lam_re dup)
__device__ ulonglong2 d_P1[N_];  // (t0r dup, t0i dup)
__device__ ulonglong2 d_P2[N_];  // (t1r dup, t1i dup)
__device__ ulonglong2 d_P3[N_];  // (t2r dup, t2i dup)
__device__ ulonglong2 d_P4[N_];  // (t3r dup, t3i dup)
__device__ uint64_t   d_Lr2[N_]; // (lam_re^2 dup)
__device__ float2 d_lamc[N_];    // (lam_re, lam_im)
__device__ float4 d_tA[N_];      // (t0r,t0i,t1r,t1i)
__device__ float4 d_tB[N_];      // (t2r,t2i,t3r,t3i)
__device__ float4 d_mom[NMOM][2];// moments
__device__ float  d_R2;          // (2*max|lam|)^2
__device__ float  d_gscale;      // 2/step
__device__ float2 d_at[L_];      // atRoots (natural order)
__device__ float2 d_GT[M_];      // G transposed: GT[a*128+b] = G[a+256b]
__device__ float2 d_stage[L_];   // FFT intermediate (only M_ used)

__device__ __forceinline__ uint64_t pack2(float lo, float hi) {
    uint64_t r;
    asm("mov.b64 %0, {%1, %2};" : "=l"(r) : "r"(__float_as_uint(lo)), "r"(__float_as_uint(hi)));
    return r;
}
__device__ __forceinline__ void unpack2(uint64_t p, float& lo, float& hi) {
    uint32_t a, b;
    asm("mov.b64 {%0, %1}, %2;" : "=r"(a), "=r"(b) : "l"(p));
    lo = __uint_as_float(a); hi = __uint_as_float(b);
}
__device__ __forceinline__ uint64_t fma2(uint64_t a, uint64_t b, uint64_t c) {
    uint64_t d;
    asm("fma.rn.f32x2 %0, %1, %2, %3;" : "=l"(d) : "l"(a), "l"(b), "l"(c));
    return d;
}
__device__ __forceinline__ uint64_t add2(uint64_t a, uint64_t b) {
    uint64_t d;
    asm("add.rn.f32x2 %0, %1, %2;" : "=l"(d) : "l"(a), "l"(b));
    return d;
}
__device__ __forceinline__ uint64_t mul2(uint64_t a, uint64_t b) {
    uint64_t d;
    asm("mul.rn.f32x2 %0, %1, %2;" : "=l"(d) : "l"(a), "l"(b));
    return d;
}
__device__ __forceinline__ float frcp(float x) {
    float r; asm("rcp.approx.f32 %0, %1;" : "=f"(r) : "f"(x)); return r;
}

// ---------------------------------------------------------------------------
// Kernel 1: Bc = Vc @ B (one block per row, coalesced), tables.
// ---------------------------------------------------------------------------
__global__ void prep_kernel(const float* __restrict__ Lre, const float* __restrict__ Lim,
                            const float* __restrict__ pre, const float* __restrict__ pim,
                            const float* __restrict__ qre, const float* __restrict__ qim,
                            const float* __restrict__ Vre, const float* __restrict__ Vim,
                            const float* __restrict__ Ct,  const float* __restrict__ B,
                            const float* __restrict__ log_step) {
    int j = blockIdx.x;
    int t = threadIdx.x;

    const float* vr = Vre + j * N_;
    const float* vi = Vim + j * N_;
    float br = 0.f, bi = 0.f;
    #pragma unroll
    for (int i = t; i < N_; i += 128) {
        float b = __ldg(B + i);
        br += vr[i] * b;
        bi += vi[i] * b;
    }
    #pragma unroll
    for (int o = 16; o > 0; o >>= 1) {
        br += __shfl_down_sync(0xffffffffu, br, o);
        bi += __shfl_down_sync(0xffffffffu, bi, o);
    }
    __shared__ float sr[4], si[4];
    int w = t >> 5;
    if ((t & 31) == 0) { sr[w] = br; si[w] = bi; }
    __syncthreads();
    if (t == 0) {
        br = sr[0] + sr[1] + sr[2] + sr[3];
        bi = si[0] + si[1] + si[2] + si[3];

        float a0r = Ct[2 * j],  a0i = -Ct[2 * j + 1];
        float a1r = qre[j],     a1i = -qim[j];
        float b1r = pre[j],     b1i = pim[j];

        float t0r = a0r * br  - a0i * bi,  t0i = a0r * bi  + a0i * br;
        float t1r = a0r * b1r - a0i * b1i, t1i = a0r * b1i + a0i * b1r;
        float t2r = a1r * br  - a1i * bi,  t2i = a1r * bi  + a1i * br;
        float t3r = a1r * b1r - a1i * b1i, t3i = a1r * b1i + a1i * b1r;

        float lr = Lre[j], li = Lim[j];
        ulonglong2 v;
        v.x = pack2(-li, -li); v.y = pack2(-lr, -lr); d_P0[j] = v;
        v.x = pack2(t0r, t0r); v.y = pack2(t0i, t0i); d_P1[j] = v;
        v.x = pack2(t1r, t1r); v.y = pack2(t1i, t1i); d_P2[j] = v;
        v.x = pack2(t2r, t2r); v.y = pack2(t2i, t2i); d_P3[j] = v;
        v.x = pack2(t3r, t3r); v.y = pack2(t3i, t3i); d_P4[j] = v;
        d_Lr2[j] = pack2(lr * lr, lr * lr);
        d_lamc[j] = make_float2(lr, li);
        d_tA[j] = make_float4(t0r, t0i, t1r, t1i);
        d_tB[j] = make_float4(t2r, t2i, t3r, t3i);
        if (j == 0) d_gscale = 2.0f / expf(log_step[0]);
    }
}

// ---------------------------------------------------------------------------
// Kernel 1b: moments C_m = sum_j t_j lam_j^m; near threshold R2.
// ---------------------------------------------------------------------------
__global__ void moments_kernel() {
    int m = blockIdx.x;
    int lane = threadIdx.x;

    float a00r = 0.f, a00i = 0.f, a01r = 0.f, a01i = 0.f;
    float a10r = 0.f, a10i = 0.f, a11r = 0.f, a11i = 0.f;
    float mx = 0.f;

    for (int i = 0; i < 16; i++) {
        int j = lane + 32 * i;
        float2 lam = d_lamc[j];
        float4 tA = d_tA[j];
        float4 tB = d_tB[j];
        float pr = 1.f, pi = 0.f, br = lam.x, bi = lam.y;
        int e = m;
        while (e) {
            if (e & 1) { float nr = pr * br - pi * bi; pi = pr * bi + pi * br; pr = nr; }
            float b2 = br * br - bi * bi; bi = 2.f * br * bi; br = b2;
            e >>= 1;
        }
        a00r += tA.x * pr - tA.y * pi;  a00i += tA.x * pi + tA.y * pr;
        a01r += tA.z * pr - tA.w * pi;  a01i += tA.z * pi + tA.w * pr;
        a10r += tB.x * pr - tB.y * pi;  a10i += tB.x * pi + tB.y * pr;
        a11r += tB.z * pr - tB.w * pi;  a11i += tB.z * pi + tB.w * pr;
        mx = fmaxf(mx, lam.x * lam.x + lam.y * lam.y);
    }
    #pragma unroll
    for (int o = 16; o > 0; o >>= 1) {
        a00r += __shfl_down_sync(0xffffffffu, a00r, o);
        a00i += __shfl_down_sync(0xffffffffu, a00i, o);
        a01r += __shfl_down_sync(0xffffffffu, a01r, o);
        a01i += __shfl_down_sync(0xffffffffu, a01i, o);
        a10r += __shfl_down_sync(0xffffffffu, a10r, o);
        a10i += __shfl_down_sync(0xffffffffu, a10i, o);
        a11r += __shfl_down_sync(0xffffffffu, a11r, o);
        a11i += __shfl_down_sync(0xffffffffu, a11i, o);
        mx = fmaxf(mx, __shfl_down_sync(0xffffffffu, mx, o));
    }
    if (lane == 0) {
        d_mom[m][0] = make_float4(a00r, a00i, a01r, a01i);
        d_mom[m][1] = make_float4(a10r, a10i, a11r, a11i);
        if (m == 0) d_R2 = 4.0f * mx;
    }
}

// ---------------------------------------------------------------------------
// Kernel 2: Cauchy -> atRoots. Block B owns l in [B*128, B*128+128).
// Near/far decided per BLOCK from interval endpoints (|tan| monotone per side).
// Near: exact f32x2 loop, j split 4-ways across warps, smem reduce.
// Far: scalar 24-term Horner in 1/g from moments.
// ---------------------------------------------------------------------------
__global__ void __launch_bounds__(256) cauchy_kernel() {
    __shared__ ulonglong2 sP0[N_];
    __shared__ ulonglong2 sP1[N_];
    __shared__ ulonglong2 sP2[N_];
    __shared__ ulonglong2 sP3[N_];
    __shared__ ulonglong2 sP4[N_];
    __shared__ uint64_t   sLr2[N_];
    __shared__ float4     smom[NMOM][2];

    int t = threadIdx.x, B = blockIdx.x;
    int base = B * 128;
    float gs = d_gscale, R2 = d_R2;

    if (t < NMOM * 2) ((float4*)smom)[t] = ((const float4*)d_mom)[t];
    __syncthreads();

    // Block-uniform near test at interval endpoints
    bool nearB;
    {
        float s, c;
        sincosf(PI_F * ((float)base * (1.0f / (float)L_)), &s, &c);
        float ya = gs * __fdividef(s, c);
        sincosf(PI_F * ((float)(base + 127) * (1.0f / (float)L_)), &s, &c);
        float yb = gs * __fdividef(s, c);
        nearB = (ya * ya < R2) || (yb * yb < R2);
    }

    if (nearB) {
        // ---- exact path ----
        #pragma unroll
        for (int i = t; i < N_; i += 256) {
            sP0[i] = d_P0[i];
            sP1[i] = d_P1[i];
            sP2[i] = d_P2[i];
            sP3[i] = d_P3[i];
            sP4[i] = d_P4[i];
            sLr2[i] = d_Lr2[i];
        }
        __syncthreads();

        int p = t & 63, chunk = t >> 6;
        int l0 = base + p, l1 = l0 + 64;
        float tan0, tan1;
        {
            float s, c;
            sincosf(PI_F * ((float)l0 * (1.0f / (float)L_)), &s, &c);
            tan0 = __fdividef(s, c);
            sincosf(PI_F * ((float)l1 * (1.0f / (float)L_)), &s, &c);
            tan1 = __fdividef(s, c);
        }
        uint64_t gi2 = pack2(gs * tan0, gs * tan1);

        uint64_t c00r = 0, c00i = 0, c01r = 0, c01i = 0;
        uint64_t c10r = 0, c10i = 0, c11r = 0, c11i = 0;
        const uint64_t SGN2 = 0x8000000080000000ull;

        int jbeg = chunk * 128, jend = jbeg + 128;
        #pragma unroll 4
        for (int j = jbeg; j < jend; j++) {
            ulonglong2 P0 = sP0[j];
            ulonglong2 P1 = sP1[j];
            ulonglong2 P2 = sP2[j];
            ulonglong2 P3 = sP3[j];
            ulonglong2 P4 = sP4[j];
            uint64_t lr2 = sLr2[j];
            uint64_t di2   = add2(gi2, P0.x);
            uint64_t n2    = fma2(di2, di2, lr2);
            float nlo, nhi;
            unpack2(n2, nlo, nhi);
            uint64_t rinv2 = pack2(frcp(nlo), frcp(nhi));
            uint64_t rr2   = mul2(P0.y, rinv2);
            uint64_t m2    = mul2(di2, rinv2);
            uint64_t nm2   = m2 ^ SGN2;

            c00r = fma2(rr2, P1.x, c00r);  c00r = fma2(m2,  P1.y, c00r);
            c00i = fma2(rr2, P1.y, c00i);  c00i = fma2(nm2, P1.x, c00i);
            c01r = fma2(rr2, P2.x, c01r);  c01r = fma2(m2,  P2.y, c01r);
            c01i = fma2(rr2, P2.y, c01i);  c01i = fma2(nm2, P2.x, c01i);
            c10r = fma2(rr2, P3.x, c10r);  c10r = fma2(m2,  P3.y, c10r);
            c10i = fma2(rr2, P3.y, c10i);  c10i = fma2(nm2, P3.x, c10i);
            c11r = fma2(rr2, P4.x, c11r);  c11r = fma2(m2,  P4.y, c11r);
            c11i = fma2(rr2, P4.y, c11i);  c11i = fma2(nm2, P4.x, c11i);
        }

        // Reduce across j-chunks (tables no longer needed -> reuse as scratch)
        __syncthreads();
        if (chunk) {
            uint64_t* area = (chunk == 1) ? (uint64_t*)sP0
                           : (chunk == 2) ? (uint64_t*)sP1 : (uint64_t*)sP2;
            area[p * 8 + 0] = c00r; area[p * 8 + 1] = c00i;
            area[p * 8 + 2] = c01r; area[p * 8 + 3] = c01i;
            area[p * 8 + 4] = c10r; area[p * 8 + 5] = c10i;
            area[p * 8 + 6] = c11r; area[p * 8 + 7] = c11i;
        }
        __syncthreads();
        if (chunk == 0) {
            const uint64_t* a1p = (const uint64_t*)sP0;
            const uint64_t* a2p = (const uint64_t*)sP1;
            const uint64_t* a3p = (const uint64_t*)sP2;
            c00r = add2(add2(c00r, a1p[p*8+0]), add2(a2p[p*8+0], a3p[p*8+0]));
            c00i = add2(add2(c00i, a1p[p*8+1]), add2(a2p[p*8+1], a3p[p*8+1]));
            c01r = add2(add2(c01r, a1p[p*8+2]), add2(a2p[p*8+2], a3p[p*8+2]));
            c01i = add2(add2(c01i, a1p[p*8+3]), add2(a2p[p*8+3], a3p[p*8+3]));
            c10r = add2(add2(c10r, a1p[p*8+4]), add2(a2p[p*8+4], a3p[p*8+4]));
            c10i = add2(add2(c10i, a1p[p*8+5]), add2(a2p[p*8+5], a3p[p*8+5]));
            c11r = add2(add2(c11r, a1p[p*8+6]), add2(a2p[p*8+6], a3p[p*8+6]));
            c11i = add2(add2(c11i, a1p[p*8+7]), add2(a2p[p*8+7], a3p[p*8+7]));

            float k00r[2], k00i[2], k01r[2], k01i[2], k10r[2], k10i[2], k11r[2], k11i[2];
            unpack2(c00r, k00r[0], k00r[1]); unpack2(c00i, k00i[0], k00i[1]);
            unpack2(c01r, k01r[0], k01r[1]); unpack2(c01i, k01i[0], k01i[1]);
            unpack2(c10r, k10r[0], k10r[1]); unpack2(c10i, k10i[0], k10i[1]);
            unpack2(c11r, k11r[0], k11r[1]); unpack2(c11i, k11i[0], k11i[1]);
            float tn[2] = {tan0, tan1};
            #pragma unroll
            for (int u = 0; u < 2; u++) {
                int l = u ? l1 : l0;
                float ddr = 1.f + k11r[u], ddi = k11i[u];
                float dinv = __fdividef(1.f, ddr * ddr + ddi * ddi);
                float qr = k01r[u] * k10r[u] - k01i[u] * k10i[u];
                float qi = k01r[u] * k10i[u] + k01i[u] * k10r[u];
                float qdr = (qr * ddr + qi * ddi) * dinv;
                float qdi = (qi * ddr - qr * ddi) * dinv;
                float ar = k00r[u] - qdr;
                float ai = k00i[u] - qdi;
                float tv = tn[u];
                d_at[l] = make_float2(ar - tv * ai, ai + tv * ar);
            }
        }
    } else if (t < 128) {
        // ---- far path: scalar Horner in w = -i/y ----
        int l = base + t;
        float s, c;
        sincosf(PI_F * ((float)l * (1.0f / (float)L_)), &s, &c);
        float tv = __fdividef(s, c);
        float y = gs * tv;
        float uu = frcp(y);

        float4 A = smom[NMOM - 1][0], Bm = smom[NMOM - 1][1];
        float h0r = A.x,  h0i = A.y,  h1r = A.z,  h1i = A.w;
        float h2r = Bm.x, h2i = Bm.y, h3r = Bm.z, h3i = Bm.w;
        #pragma unroll
        for (int m = NMOM - 2; m >= 0; m--) {
            float4 A2 = smom[m][0], B2 = smom[m][1];
            float n0r = fmaf(h0i, uu, A2.x), n0i = fmaf(-h0r, uu, A2.y);
            float n1r = fmaf(h1i, uu, A2.z), n1i = fmaf(-h1r, uu, A2.w);
            float n2r = fmaf(h2i, uu, B2.x), n2i = fmaf(-h2r, uu, B2.y);
            float n3r = fmaf(h3i, uu, B2.z), n3i = fmaf(-h3r, uu, B2.w);
            h0r = n0r; h0i = n0i; h1r = n1r; h1i = n1i;
            h2r = n2r; h2i = n2i; h3r = n3r; h3i = n3i;
        }
        float k00r = h0i * uu,  k00i = -h0r * uu;
        float k01r = h1i * uu,  k01i = -h1r * uu;
        float k10r = h2i * uu,  k10i = -h2r * uu;
        float k11r = h3i * uu,  k11i = -h3r * uu;

        float ddr = 1.f + k11r, ddi = k11i;
        float dinv = __fdividef(1.f, ddr * ddr + ddi * ddi);
        float qr = k01r * k10r - k01i * k10i;
        float qi = k01r * k10i + k01i * k10r;
        float qdr = (qr * ddr + qi * ddi) * dinv;
        float qdi = (qi * ddr - qr * ddi) * dinv;
        float ar = k00r - qdr;
        float ai = k00i - qdi;
        d_at[l] = make_float2(ar - tv * ai, ai + tv * ar);
    }
}

// ---------------------------------------------------------------------------
// Kernel 3: build G (real-IFFT fold) with coalesced loads; store transposed.
//   G[k] = (X[k]+conj(X[L-k]))(1+i w_k) + (X[k+M]+conj(X[M-k]))(1-i w_k)
//   GT[(k&255)*128 + (k>>8)] = G[k]
// ---------------------------------------------------------------------------
__global__ void __launch_bounds__(256) g_kernel() {
    int k = blockIdx.x * 256 + threadIdx.x;
    float2 X1 = d_at[k];
    float2 X2 = d_at[(L_ - k) & (L_ - 1)];
    float2 X3 = d_at[k + M_];
    float2 X4 = d_at[M_ - k];
    float Ar = X1.x + X2.x, Ai = X1.y - X2.y;
    float Br = X3.x + X4.x, Bi = X3.y - X4.y;
    float ws, wc;
    __sincosf(TWO_PI * ((float)k * (1.0f / (float)L_)), &ws, &wc);
    float Qr = Ar - Br, Qi = Ai - Bi;
    float wqr = wc * Qr - ws * Qi;
    float wqi = wc * Qi + ws * Qr;
    d_GT[(k & 255) * 128 + (k >> 8)] =
        make_float2(Ar + Br - wqi, Ai + Bi + wqr);
}

// ---------------------------------------------------------------------------
// Complex IFFT of length M = 256 x 128, four-step.
// step1: 128-pt DFT over b for each a; twiddle W_M^{ac}; transpose-store.
// ---------------------------------------------------------------------------
__global__ void __launch_bounds__(128) fft_step1() {
    __shared__ float2 sx[128];
    __shared__ float2 sw[128];       // e^{+2pi i k/128}
    __shared__ float2 sz[16 * 9];    // padded
    int a = blockIdx.x, t = threadIdx.x;   // t = b index

    sx[t] = d_GT[a * 128 + t];       // coalesced
    {
        float s, c;
        __sincosf(TWO_PI * ((float)t * (1.0f / 128.0f)), &s, &c);
        sw[t] = make_float2(c, s);
    }
    __syncthreads();

    // Stage A: z[b1][c1] over b2 in [0,8): b1 in 16, c1 in 8
    {
        int b1 = t & 15, c1 = t >> 4;
        float xr = 0.f, xi = 0.f;
        #pragma unroll
        for (int b2 = 0; b2 < 8; b2++) {
            float2 x = sx[b1 + 16 * b2];
            float2 w = sw[(16 * b2 * c1) & 127];
            xr += x.x * w.x - x.y * w.y;
            xi += x.x * w.y + x.y * w.x;
        }
        float2 tw = sw[(b1 * c1) & 127];
        sz[b1 * 9 + c1] = make_float2(xr * tw.x - xi * tw.y,
                                      xr * tw.y + xi * tw.x);
    }
    __syncthreads();

    // Stage B: S[c1 + 8 c2] = sum_b1 z[b1][c1] W16^{b1 c2};  c = t
    {
        int c1 = t & 7, c2 = t >> 3;
        float yr = 0.f, yi = 0.f;
        #pragma unroll
        for (int b1 = 0; b1 < 16; b1++) {
            float2 z = sz[b1 * 9 + c1];
            float2 w = sw[(8 * b1 * c2) & 127];
            yr += z.x * w.x - z.y * w.y;
            yi += z.x * w.y + z.y * w.x;
        }
        int m = (a * t) & (M_ - 1);
        float ws, wc;
        __sincosf(TWO_PI * ((float)m * (1.0f / (float)M_)), &ws, &wc);
        d_stage[t * 256 + a] = make_float2(yr * wc - yi * ws,
                                           yr * ws + yi * wc);
    }
}

__global__ void __launch_bounds__(256) fft_step2(float2* __restrict__ out) {
    __shared__ float2 sx[256];
    __shared__ float2 sw[256];
    __shared__ float2 sz[16 * 17];
    int c = blockIdx.x, t = threadIdx.x;   // t = d index

    sx[t] = d_stage[c * 256 + t];
    {
        float s, cc;
        __sincosf(TWO_PI * ((float)t * (1.0f / 256.0f)), &s, &cc);
        sw[t] = make_float2(cc, s);
    }
    __syncthreads();

    {
        int a1 = t & 15, d1 = t >> 4;
        float xr = 0.f, xi = 0.f;
        #pragma unroll
        for (int a2 = 0; a2 < 16; a2++) {
            float2 x = sx[a1 + 16 * a2];
            float2 w = sw[(16 * a2 * d1) & 255];
            xr += x.x * w.x - x.y * w.y;
            xi += x.x * w.y + x.y * w.x;
        }
        float2 tw = sw[a1 * d1];
        sz[a1 * 17 + d1] = make_float2(xr * tw.x - xi * tw.y,
                                       xr * tw.y + xi * tw.x);
    }
    __syncthreads();

    {
        int d1 = t & 15, d2 = t >> 4;
        float yr = 0.f, yi = 0.f;
        #pragma unroll
        for (int a1 = 0; a1 < 16; a1++) {
            float2 z = sz[a1 * 17 + d1];
            float2 w = sw[(16 * a1 * d2) & 255];
            yr += z.x * w.x - z.y * w.y;
            yi += z.x * w.y + z.y * w.x;
        }
        const float sc = 1.0f / (2.0f * (float)L_);
        out[c + 128 * t] = make_float2(yr * sc, yi * sc);
    }
}

// ---------------------------------------------------------------------------
extern "C" void kernel_launch(void* const* d_in, const int* in_sizes, int n_in,
                              void* d_out, int out_size) {
    const float* Lambda_re = (const float*)d_in[0];
    const float* Lambda_im = (const float*)d_in[1];
    const float* p_re      = (const float*)d_in[2];
    const float* p_im      = (const float*)d_in[3];
    const float* q_re      = (const float*)d_in[4];
    const float* q_im      = (const float*)d_in[5];
    const float* Vc_re     = (const float*)d_in[6];
    const float* Vc_im     = (const float*)d_in[7];
    const float* Ct        = (const float*)d_in[8];
    const float* B         = (const float*)d_in[9];
    const float* log_step  = (const float*)d_in[10];

    prep_kernel<<<N_, 128>>>(Lambda_re, Lambda_im, p_re, p_im, q_re, q_im,
                             Vc_re, Vc_im, Ct, B, log_step);
    moments_kernel<<<NMOM, 32>>>();
    cauchy_kernel<<<512, 256>>>();
    g_kernel<<<M_ / 256, 256>>>();
    fft_step1<<<256, 128>>>();
    fft_step2<<<128, 256>>>((float2*)d_out);
}